// round 8
// baseline (speedup 1.0000x reference)
#include <cuda_runtime.h>
#include <cuda_bf16.h>
#include <math.h>
#include <stdint.h>

#define BB   2
#define TT   2048
#define HH   16
#define DKD  64
#define DMD  1024
#define MTOT (BB*TT)

// ---------------- device scratch (no allocations allowed) -------------------
__device__ float g_cos[TT*(DKD/2)];
__device__ float g_sin[TT*(DKD/2)];

__device__ __nv_bfloat16 gx_hi[MTOT*DMD];
__device__ __nv_bfloat16 gx_lo[MTOT*DMD];
__device__ __nv_bfloat16 gw_hi[4*DMD*DMD];
__device__ __nv_bfloat16 gw_lo[4*DMD*DMD];
__device__ __nv_bfloat16 gctx_hi[MTOT*DMD];
__device__ __nv_bfloat16 gctx_lo[MTOT*DMD];

__device__ __nv_bfloat16 g_qh[BB*HH*TT*DKD];
__device__ __nv_bfloat16 g_ql[BB*HH*TT*DKD];
__device__ __nv_bfloat16 g_kh[BB*HH*TT*DKD];
__device__ __nv_bfloat16 g_kl[BB*HH*TT*DKD];
__device__ __nv_bfloat16 g_vth[BB*HH*TT*DKD];   // [B,H,64,T]
__device__ __nv_bfloat16 g_vtl[BB*HH*TT*DKD];

// ---------------- helpers -----------------------------------------------------
__device__ __forceinline__ uint32_t smem_u32(const void* p) {
    uint32_t a;
    asm("{ .reg .u64 t; cvta.to.shared.u64 t, %1; cvt.u32.u64 %0, t; }"
        : "=r"(a) : "l"(p));
    return a;
}
__device__ __forceinline__ void cp_async16(uint32_t dst, const void* src) {
    asm volatile("cp.async.cg.shared.global [%0], [%1], 16;"
                 :: "r"(dst), "l"(src) : "memory");
}
#define CP_COMMIT() asm volatile("cp.async.commit_group;" ::: "memory")
#define CP_WAIT(n)  asm volatile("cp.async.wait_group %0;" :: "n"(n) : "memory")

#define LDMX4(r0, r1, r2, r3, addr) \
    asm volatile("ldmatrix.sync.aligned.m8n8.x4.shared.b16 {%0,%1,%2,%3}, [%4];" \
        : "=r"(r0), "=r"(r1), "=r"(r2), "=r"(r3) : "r"(addr))

#define MMA_BF16(d, a0, a1, a2, a3, b0, b1) \
    asm volatile("mma.sync.aligned.m16n8k16.row.col.f32.bf16.bf16.f32 " \
        "{%0,%1,%2,%3}, {%4,%5,%6,%7}, {%8,%9}, {%0,%1,%2,%3};" \
        : "+f"((d)[0]), "+f"((d)[1]), "+f"((d)[2]), "+f"((d)[3]) \
        : "r"(a0), "r"(a1), "r"(a2), "r"(a3), "r"(b0), "r"(b1))

__device__ __forceinline__ void split2(float x, float y, uint32_t &hi, uint32_t &lo) {
    __nv_bfloat16 hx = __float2bfloat16(x);
    __nv_bfloat16 hy = __float2bfloat16(y);
    float rx = x - __bfloat162float(hx);
    float ry = y - __bfloat162float(hy);
    __nv_bfloat162 h; h.x = hx; h.y = hy;
    __nv_bfloat162 l; l.x = __float2bfloat16(rx); l.y = __float2bfloat16(ry);
    hi = *(uint32_t*)&h;
    lo = *(uint32_t*)&l;
}

// ---------------- fused prep: all cvts + rope tables in ONE launch -------------
#define NX2_BLK 8192
#define NW2_BLK 2048
#define PREP_BLOCKS (NX2_BLK + 4*NW2_BLK + 256)

__global__ void prep_kernel(const float2* __restrict__ x,
                            const float2* __restrict__ w0,
                            const float2* __restrict__ w1,
                            const float2* __restrict__ w2,
                            const float2* __restrict__ w3)
{
    const int blk = blockIdx.x;
    if (blk < NX2_BLK) {
        const int i = blk * 256 + threadIdx.x;
        float2 v = x[i];
        uint32_t h, l;
        split2(v.x, v.y, h, l);
        *(uint32_t*)((__nv_bfloat162*)gx_hi + i) = h;
        *(uint32_t*)((__nv_bfloat162*)gx_lo + i) = l;
    } else if (blk < NX2_BLK + 4 * NW2_BLK) {
        const int wsel = (blk - NX2_BLK) / NW2_BLK;
        const int i = ((blk - NX2_BLK) % NW2_BLK) * 256 + threadIdx.x;
        const float2* w = (wsel == 0) ? w0 : (wsel == 1) ? w1 : (wsel == 2) ? w2 : w3;
        float2 v = w[i];
        uint32_t h, l;
        split2(v.x, v.y, h, l);
        const size_t off = (size_t)wsel << 19;
        *(uint32_t*)((__nv_bfloat162*)gw_hi + off + i) = h;
        *(uint32_t*)((__nv_bfloat162*)gw_lo + off + i) = l;
    } else {
        const int idx = (blk - NX2_BLK - 4 * NW2_BLK) * 256 + threadIdx.x;
        const int t = idx >> 5;
        const int i = idx & 31;
        double inv = pow(10000.0, -((double)(2 * i)) / 64.0);
        double ang = (double)t * inv;
        g_cos[idx] = (float)cos(ang);
        g_sin[idx] = (float)sin(ang);
    }
}

// ---------------- mma.sync bf16 split GEMM: C = A * W^T ------------------------
// CTA tile 128x128, 8 warps (2x4), warp tile 64x32.
// K chunks of 16, 48B rows, 4 stages, ONE sync per chunk, 2 CTAs/SM.
#define ROWB     48
#define TILE_B   (128 * ROWB)                // 6144
#define STAGE_B  (4 * TILE_B)                // 24576
#define GEMM_SMEM (4 * STAGE_B)              // 98304

template <int QKV>
__global__ void __launch_bounds__(256, 2)
mma_gemm(float* __restrict__ Cout)
{
    extern __shared__ char smem_raw[];
    const uint32_t sb = smem_u32(smem_raw);

    const int tid = threadIdx.x;
    const int wid = tid >> 5;
    const int lid = tid & 31;
    const int n0 = blockIdx.x * 128;
    const int m0 = blockIdx.y * 128;
    const int z  = QKV ? (int)blockIdx.z : 3;

    const __nv_bfloat16* Ah = QKV ? gx_hi : gctx_hi;
    const __nv_bfloat16* Al = QKV ? gx_lo : gctx_lo;
    const __nv_bfloat16* Wh = gw_hi + ((size_t)z << 20);
    const __nv_bfloat16* Wl = gw_lo + ((size_t)z << 20);

    const __nv_bfloat16* Ah_m = Ah + (size_t)m0 * DMD;
    const __nv_bfloat16* Al_m = Al + (size_t)m0 * DMD;
    const __nv_bfloat16* Wh_n = Wh + (size_t)n0 * DMD;
    const __nv_bfloat16* Wl_n = Wl + (size_t)n0 * DMD;

    // loader: 256 threads; per 128x16 tile: 128 rows x 2 chunks of 16B
    const int llr = tid >> 1;            // 0..127
    const int llc = tid & 1;             // 0..1

    auto load_chunk = [&](int kc, int s) {
        const uint32_t stage = sb + (uint32_t)s * STAGE_B;
        const size_t koff = (size_t)kc * 16 + (size_t)llc * 8;
        const uint32_t so = (uint32_t)llr * ROWB + (uint32_t)llc * 16;
        cp_async16(stage + so,              Ah_m + (size_t)llr * DMD + koff);
        cp_async16(stage + TILE_B + so,     Al_m + (size_t)llr * DMD + koff);
        cp_async16(stage + 2 * TILE_B + so, Wh_n + (size_t)llr * DMD + koff);
        cp_async16(stage + 3 * TILE_B + so, Wl_n + (size_t)llr * DMD + koff);
        CP_COMMIT();
    };

    const int wm = wid >> 2;
    const int wn = wid & 3;
    const int lt  = lid >> 3;
    const int lrw = lid & 7;

    const uint32_t a_off = (uint32_t)(wm * 64 + (lt & 1) * 8 + lrw) * ROWB
                         + (uint32_t)(lt >> 1) * 16;
    const uint32_t b_off = (uint32_t)(wn * 32 + (lt & 1) * 8 + lrw) * ROWB
                         + (uint32_t)(lt >> 1) * 16;

    float acc[4][4][4];
#pragma unroll
    for (int i = 0; i < 4; i++)
#pragma unroll
        for (int j = 0; j < 4; j++)
#pragma unroll
            for (int r = 0; r < 4; r++) acc[i][j][r] = 0.0f;

    load_chunk(0, 0);
    load_chunk(1, 1);
    load_chunk(2, 2);

    for (int c = 0; c < 64; ++c) {
        if (c < 62) {
            CP_WAIT(2);
        } else {
            CP_WAIT(0);
        }
        __syncthreads();
        if (c + 3 < 64) load_chunk(c + 3, (c + 3) & 3);

        const uint32_t stage = sb + (uint32_t)(c & 3) * STAGE_B;
        const uint32_t ah_base = stage + a_off;
        const uint32_t al_base = stage + TILE_B + a_off;
        const uint32_t bh_base = stage + 2 * TILE_B + b_off;
        const uint32_t bl_base = stage + 3 * TILE_B + b_off;

        uint32_t ah[4][4], al[4][4], bh[2][4], bl[2][4];
#pragma unroll
        for (int mf = 0; mf < 4; ++mf) {
            LDMX4(ah[mf][0], ah[mf][1], ah[mf][2], ah[mf][3],
                  ah_base + (uint32_t)mf * (16 * ROWB));
            LDMX4(al[mf][0], al[mf][1], al[mf][2], al[mf][3],
                  al_base + (uint32_t)mf * (16 * ROWB));
        }
#pragma unroll
        for (int nn = 0; nn < 2; ++nn) {
            LDMX4(bh[nn][0], bh[nn][1], bh[nn][2], bh[nn][3],
                  bh_base + (uint32_t)nn * (16 * ROWB));
            LDMX4(bl[nn][0], bl[nn][1], bl[nn][2], bl[nn][3],
                  bl_base + (uint32_t)nn * (16 * ROWB));
        }
#pragma unroll
        for (int mf = 0; mf < 4; ++mf) {
#pragma unroll
            for (int nf = 0; nf < 4; ++nf) {
                const int nn = nf >> 1;
                const int sel = nf & 1;
                MMA_BF16(acc[mf][nf], ah[mf][0], ah[mf][1], ah[mf][2], ah[mf][3],
                         bh[nn][sel], bh[nn][2 + sel]);
                MMA_BF16(acc[mf][nf], ah[mf][0], ah[mf][1], ah[mf][2], ah[mf][3],
                         bl[nn][sel], bl[nn][2 + sel]);
                MMA_BF16(acc[mf][nf], al[mf][0], al[mf][1], al[mf][2], al[mf][3],
                         bh[nn][sel], bh[nn][2 + sel]);
            }
        }
    }

    // ---------------- epilogue ----------------
    const int rbase = m0 + wm * 64 + (lid >> 2);
    const int cbase = n0 + wn * 32 + (lid & 3) * 2;

#pragma unroll
    for (int mf = 0; mf < 4; ++mf) {
#pragma unroll
        for (int nf = 0; nf < 4; ++nf) {
#pragma unroll
            for (int half = 0; half < 2; ++half) {
                const int m = rbase + mf * 16 + half * 8;
                const int n = cbase + nf * 8;
                const float x = acc[mf][nf][half * 2 + 0];
                const float y = acc[mf][nf][half * 2 + 1];
                if (QKV == 0) {
                    *(float2*)(Cout + (size_t)m * DMD + n) = make_float2(x, y);
                } else {
                    const int b = m >> 11;
                    const int t = m & (TT - 1);
                    const int h = n >> 6;
                    const int d = n & 63;
                    const size_t bh = (size_t)(b * HH + h);
                    if (z < 2) {
                        const float cs = g_cos[t * 32 + (d >> 1)];
                        const float sn = g_sin[t * 32 + (d >> 1)];
                        float rx = x * cs - y * sn;
                        float ry = x * sn + y * cs;
                        if (z == 0) { rx *= 0.125f; ry *= 0.125f; }
                        uint32_t hv, lv;
                        split2(rx, ry, hv, lv);
                        const size_t idx = (bh * TT + t) * DKD + d;
                        if (z == 0) {
                            *(uint32_t*)(g_qh + idx) = hv;
                            *(uint32_t*)(g_ql + idx) = lv;
                        } else {
                            *(uint32_t*)(g_kh + idx) = hv;
                            *(uint32_t*)(g_kl + idx) = lv;
                        }
                    } else {
                        __nv_bfloat16 hx = __float2bfloat16(x);
                        __nv_bfloat16 hy = __float2bfloat16(y);
                        const size_t ix = (bh * DKD + d) * TT + t;
                        g_vth[ix]      = hx;
                        g_vtl[ix]      = __float2bfloat16(x - __bfloat162float(hx));
                        g_vth[ix + TT] = hy;
                        g_vtl[ix + TT] = __float2bfloat16(y - __bfloat162float(hy));
                    }
                }
            }
        }
    }
}

// ---------------- tensor-core causal flash attention (R4-proven core) ----------
// Now 2 CTAs/SM for latency hiding.
#define AROWB 144
#define ATILE (64 * AROWB)          // 9216
#define ATT_SMEM (10 * ATILE)       // 92160: Qh,Ql + 2 stages * (Kh,Kl,Vth,Vtl)

__global__ void __launch_bounds__(128, 2)
attn_kernel()
{
    extern __shared__ char smem_raw[];
    const uint32_t sb = smem_u32(smem_raw);
    const uint32_t stages = sb + 2 * ATILE;

    const int h   = blockIdx.x;
    const int b   = blockIdx.y;
    const int qt  = (int)(gridDim.z - 1 - blockIdx.z);   // heavy tiles first
    const int tid = threadIdx.x;
    const int wq  = tid >> 5;
    const int lid = tid & 31;

    const size_t bh = (size_t)(b * HH + h);
    const __nv_bfloat16* qh_g = g_qh + (bh * TT + (size_t)qt * 64) * DKD;
    const __nv_bfloat16* ql_g = g_ql + (bh * TT + (size_t)qt * 64) * DKD;
    const __nv_bfloat16* kh_g = g_kh + bh * TT * DKD;
    const __nv_bfloat16* kl_g = g_kl + bh * TT * DKD;
    const __nv_bfloat16* vh_g = g_vth + bh * DKD * TT;
    const __nv_bfloat16* vl_g = g_vtl + bh * DKD * TT;

#pragma unroll
    for (int i = 0; i < 4; ++i) {
        int cid = i * 128 + tid;
        int r = cid >> 3, c = cid & 7;
        cp_async16(sb + (uint32_t)r * AROWB + (uint32_t)c * 16,
                   qh_g + (size_t)r * DKD + c * 8);
        cp_async16(sb + ATILE + (uint32_t)r * AROWB + (uint32_t)c * 16,
                   ql_g + (size_t)r * DKD + c * 8);
    }
    CP_COMMIT();

    auto load_kv = [&](int kt, int s) {
        const uint32_t stage = stages + (uint32_t)s * (4 * ATILE);
#pragma unroll
        for (int i = 0; i < 4; ++i) {
            int cid = i * 128 + tid;
            int r = cid >> 3, c = cid & 7;
            const uint32_t so = (uint32_t)r * AROWB + (uint32_t)c * 16;
            const size_t kk = (size_t)(kt * 64 + r) * DKD + c * 8;
            const size_t vv = (size_t)r * TT + kt * 64 + c * 8;
            cp_async16(stage + so,             kh_g + kk);
            cp_async16(stage + ATILE + so,     kl_g + kk);
            cp_async16(stage + 2 * ATILE + so, vh_g + vv);
            cp_async16(stage + 3 * ATILE + so, vl_g + vv);
        }
        CP_COMMIT();
    };

    const int lt  = lid >> 3;
    const int lrw = lid & 7;
    const uint32_t a_off = (uint32_t)(wq * 16 + (lt & 1) * 8 + lrw) * AROWB
                         + (uint32_t)(lt >> 1) * 16;
    uint32_t bn_off[4];
#pragma unroll
    for (int nn = 0; nn < 4; ++nn)
        bn_off[nn] = (uint32_t)(nn * 16 + (lt & 1) * 8 + lrw) * AROWB
                   + (uint32_t)(lt >> 1) * 16;

    load_kv(0, 0);

    CP_WAIT(1);
    __syncthreads();
    uint32_t qfh[4][4], qfl[4][4];
#pragma unroll
    for (int ks = 0; ks < 4; ++ks) {
        LDMX4(qfh[ks][0], qfh[ks][1], qfh[ks][2], qfh[ks][3], sb + a_off + ks * 32);
        LDMX4(qfl[ks][0], qfl[ks][1], qfl[ks][2], qfl[ks][3], sb + ATILE + a_off + ks * 32);
    }

    float O[8][4];
#pragma unroll
    for (int i = 0; i < 8; ++i)
#pragma unroll
        for (int j = 0; j < 4; ++j) O[i][j] = 0.0f;
    float m0v = -1e30f, m1v = -1e30f, l0 = 0.0f, l1 = 0.0f;

    for (int kt = 0; kt <= qt; ++kt) {
        const int s = kt & 1;
        if (kt < qt) {
            load_kv(kt + 1, s ^ 1);
            CP_WAIT(1);
        } else {
            CP_WAIT(0);
        }
        __syncthreads();

        const uint32_t stage = stages + (uint32_t)s * (4 * ATILE);

        float S[8][4];
#pragma unroll
        for (int i = 0; i < 8; ++i)
#pragma unroll
            for (int j = 0; j < 4; ++j) S[i][j] = 0.0f;

#pragma unroll
        for (int ks = 0; ks < 4; ++ks) {
            uint32_t kh[4][4], kl[4][4];
#pragma unroll
            for (int nn = 0; nn < 4; ++nn) {
                LDMX4(kh[nn][0], kh[nn][1], kh[nn][2], kh[nn][3],
                      stage + bn_off[nn] + ks * 32);
                LDMX4(kl[nn][0], kl[nn][1], kl[nn][2], kl[nn][3],
                      stage + ATILE + bn_off[nn] + ks * 32);
            }
#pragma unroll
            for (int nf = 0; nf < 8; ++nf) {
                const int nn = nf >> 1;
                const int sel = nf & 1;
                MMA_BF16(S[nf], qfh[ks][0], qfh[ks][1], qfh[ks][2], qfh[ks][3],
                         kh[nn][sel], kh[nn][2 + sel]);
                MMA_BF16(S[nf], qfh[ks][0], qfh[ks][1], qfh[ks][2], qfh[ks][3],
                         kl[nn][sel], kl[nn][2 + sel]);
                MMA_BF16(S[nf], qfl[ks][0], qfl[ks][1], qfl[ks][2], qfl[ks][3],
                         kh[nn][sel], kh[nn][2 + sel]);
            }
        }

        if (kt == qt) {
            const int row0 = wq * 16 + (lid >> 2);
            const int colb = (lid & 3) * 2;
#pragma unroll
            for (int nf = 0; nf < 8; ++nf) {
                const int c0 = nf * 8 + colb;
                if (c0     > row0)     S[nf][0] = -1e30f;
                if (c0 + 1 > row0)     S[nf][1] = -1e30f;
                if (c0     > row0 + 8) S[nf][2] = -1e30f;
                if (c0 + 1 > row0 + 8) S[nf][3] = -1e30f;
            }
        }

        float r0 = -1e30f, r1 = -1e30f;
#pragma unroll
        for (int nf = 0; nf < 8; ++nf) {
            r0 = fmaxf(r0, fmaxf(S[nf][0], S[nf][1]));
            r1 = fmaxf(r1, fmaxf(S[nf][2], S[nf][3]));
        }
        r0 = fmaxf(r0, __shfl_xor_sync(0xffffffffu, r0, 1));
        r0 = fmaxf(r0, __shfl_xor_sync(0xffffffffu, r0, 2));
        r1 = fmaxf(r1, __shfl_xor_sync(0xffffffffu, r1, 1));
        r1 = fmaxf(r1, __shfl_xor_sync(0xffffffffu, r1, 2));

        const float nm0 = fmaxf(m0v, r0);
        const float nm1 = fmaxf(m1v, r1);
        const float a0 = __expf(m0v - nm0);
        const float a1 = __expf(m1v - nm1);
        m0v = nm0; m1v = nm1;

        float rs0 = 0.0f, rs1 = 0.0f;
#pragma unroll
        for (int nf = 0; nf < 8; ++nf) {
            S[nf][0] = __expf(S[nf][0] - m0v);
            S[nf][1] = __expf(S[nf][1] - m0v);
            S[nf][2] = __expf(S[nf][2] - m1v);
            S[nf][3] = __expf(S[nf][3] - m1v);
            rs0 += S[nf][0] + S[nf][1];
            rs1 += S[nf][2] + S[nf][3];
        }
        rs0 += __shfl_xor_sync(0xffffffffu, rs0, 1);
        rs0 += __shfl_xor_sync(0xffffffffu, rs0, 2);
        rs1 += __shfl_xor_sync(0xffffffffu, rs1, 1);
        rs1 += __shfl_xor_sync(0xffffffffu, rs1, 2);
        l0 = l0 * a0 + rs0;
        l1 = l1 * a1 + rs1;

#pragma unroll
        for (int nf = 0; nf < 8; ++nf) {
            O[nf][0] *= a0; O[nf][1] *= a0;
            O[nf][2] *= a1; O[nf][3] *= a1;
        }

#pragma unroll
        for (int kb2 = 0; kb2 < 4; ++kb2) {
            uint32_t ph[4], pl[4];
            split2(S[2 * kb2][0],     S[2 * kb2][1],     ph[0], pl[0]);
            split2(S[2 * kb2][2],     S[2 * kb2][3],     ph[1], pl[1]);
            split2(S[2 * kb2 + 1][0], S[2 * kb2 + 1][1], ph[2], pl[2]);
            split2(S[2 * kb2 + 1][2], S[2 * kb2 + 1][3], ph[3], pl[3]);

            uint32_t vh[4][4], vl[4][4];
#pragma unroll
            for (int nn = 0; nn < 4; ++nn) {
                LDMX4(vh[nn][0], vh[nn][1], vh[nn][2], vh[nn][3],
                      stage + 2 * ATILE + bn_off[nn] + kb2 * 32);
                LDMX4(vl[nn][0], vl[nn][1], vl[nn][2], vl[nn][3],
                      stage + 3 * ATILE + bn_off[nn] + kb2 * 32);
            }
#pragma unroll
            for (int nf = 0; nf < 8; ++nf) {
                const int nn = nf >> 1;
                const int sel = nf & 1;
                MMA_BF16(O[nf], ph[0], ph[1], ph[2], ph[3],
                         vh[nn][sel], vh[nn][2 + sel]);
                MMA_BF16(O[nf], ph[0], ph[1], ph[2], ph[3],
                         vl[nn][sel], vl[nn][2 + sel]);
                MMA_BF16(O[nf], pl[0], pl[1], pl[2], pl[3],
                         vh[nn][sel], vh[nn][2 + sel]);
            }
        }
        __syncthreads();
    }

    const float i0 = 1.0f / l0;
    const float i1 = 1.0f / l1;
    const int q0 = qt * 64 + wq * 16 + (lid >> 2);
    const int colb = (lid & 3) * 2;
#pragma unroll
    for (int nf = 0; nf < 8; ++nf) {
        const int d = nf * 8 + colb;
        uint32_t hv, lv;
        size_t idx = ((size_t)b * TT + q0) * DMD + h * DKD + d;
        split2(O[nf][0] * i0, O[nf][1] * i0, hv, lv);
        *(uint32_t*)(gctx_hi + idx) = hv;
        *(uint32_t*)(gctx_lo + idx) = lv;
        idx += (size_t)8 * DMD;
        split2(O[nf][2] * i1, O[nf][3] * i1, hv, lv);
        *(uint32_t*)(gctx_hi + idx) = hv;
        *(uint32_t*)(gctx_lo + idx) = lv;
    }
}

// ---------------- launch ---------------------------------------------------------
extern "C" void kernel_launch(void* const* d_in, const int* in_sizes, int n_in,
                              void* d_out, int out_size)
{
    const float* x   = (const float*)d_in[0];
    const float* w_q = (const float*)d_in[1];
    const float* w_k = (const float*)d_in[2];
    const float* w_v = (const float*)d_in[3];
    const float* w_o = (const float*)d_in[4];
    float* out = (float*)d_out;

    static int configured = 0;
    if (!configured) {
        cudaFuncSetAttribute(mma_gemm<1>, cudaFuncAttributeMaxDynamicSharedMemorySize, GEMM_SMEM);
        cudaFuncSetAttribute(mma_gemm<0>, cudaFuncAttributeMaxDynamicSharedMemorySize, GEMM_SMEM);
        cudaFuncSetAttribute(attn_kernel, cudaFuncAttributeMaxDynamicSharedMemorySize, ATT_SMEM);
        configured = 1;
    }

    prep_kernel<<<PREP_BLOCKS, 256>>>((const float2*)x, (const float2*)w_q,
                                      (const float2*)w_k, (const float2*)w_v,
                                      (const float2*)w_o);

    mma_gemm<1><<<dim3(DMD / 128, MTOT / 128, 3), 256, GEMM_SMEM>>>(nullptr);

    attn_kernel<<<dim3(HH, BB, TT / 64), 128, ATT_SMEM>>>();

    mma_gemm<0><<<dim3(DMD / 128, MTOT / 128, 1), 256, GEMM_SMEM>>>(out);
}

// round 9
// speedup vs baseline: 1.5288x; 1.5288x over previous
#include <cuda_runtime.h>
#include <cuda_fp16.h>
#include <math.h>
#include <stdint.h>

#define BB   2
#define TT   2048
#define HH   16
#define DKD  64
#define DMD  1024
#define MTOT (BB*TT)

// ---------------- device scratch (no allocations allowed) -------------------
__device__ float g_cos[TT*(DKD/2)];
__device__ float g_sin[TT*(DKD/2)];

// fp16 operands: A-side hi only, B-side hi+lo
__device__ __half gx_h [MTOT*DMD];
__device__ __half gw_h [4*DMD*DMD];
__device__ __half gw_l [4*DMD*DMD];
__device__ __half gctx_h[MTOT*DMD];

__device__ __half g_qh [BB*HH*TT*DKD];     // A-side (hi only, scale folded)
__device__ __half g_kh [BB*HH*TT*DKD];     // B-side hi
__device__ __half g_kl [BB*HH*TT*DKD];     // B-side lo
__device__ __half g_vth[BB*HH*TT*DKD];     // [B,H,64,T] hi
__device__ __half g_vtl[BB*HH*TT*DKD];     // [B,H,64,T] lo

// ---------------- helpers -----------------------------------------------------
__device__ __forceinline__ uint32_t smem_u32(const void* p) {
    uint32_t a;
    asm("{ .reg .u64 t; cvta.to.shared.u64 t, %1; cvt.u32.u64 %0, t; }"
        : "=r"(a) : "l"(p));
    return a;
}
__device__ __forceinline__ void cp_async16(uint32_t dst, const void* src) {
    asm volatile("cp.async.cg.shared.global [%0], [%1], 16;"
                 :: "r"(dst), "l"(src) : "memory");
}
#define CP_COMMIT() asm volatile("cp.async.commit_group;" ::: "memory")
#define CP_WAIT(n)  asm volatile("cp.async.wait_group %0;" :: "n"(n) : "memory")

#define LDMX4(r0, r1, r2, r3, addr) \
    asm volatile("ldmatrix.sync.aligned.m8n8.x4.shared.b16 {%0,%1,%2,%3}, [%4];" \
        : "=r"(r0), "=r"(r1), "=r"(r2), "=r"(r3) : "r"(addr))

#define MMA_F16(d, a0, a1, a2, a3, b0, b1) \
    asm volatile("mma.sync.aligned.m16n8k16.row.col.f32.f16.f16.f32 " \
        "{%0,%1,%2,%3}, {%4,%5,%6,%7}, {%8,%9}, {%0,%1,%2,%3};" \
        : "+f"((d)[0]), "+f"((d)[1]), "+f"((d)[2]), "+f"((d)[3]) \
        : "r"(a0), "r"(a1), "r"(a2), "r"(a3), "r"(b0), "r"(b1))

__device__ __forceinline__ uint32_t packh2(float x, float y) {
    __half2 h = __floats2half2_rn(x, y);
    return *(uint32_t*)&h;
}
// split two floats into fp16 hi and lo packed words
__device__ __forceinline__ void splith2(float x, float y, uint32_t &hi, uint32_t &lo) {
    __half hx = __float2half_rn(x);
    __half hy = __float2half_rn(y);
    float rx = x - __half2float(hx);
    float ry = y - __half2float(hy);
    __half2 h; h.x = hx; h.y = hy;
    __half2 l = __floats2half2_rn(rx, ry);
    hi = *(uint32_t*)&h;
    lo = *(uint32_t*)&l;
}

// ---------------- fused prep: x hi, weights hi+lo, rope tables -----------------
#define NX2_BLK 8192
#define NW2_BLK 2048
#define PREP_BLOCKS (NX2_BLK + 4*NW2_BLK + 256)

__global__ void prep_kernel(const float2* __restrict__ x,
                            const float2* __restrict__ w0,
                            const float2* __restrict__ w1,
                            const float2* __restrict__ w2,
                            const float2* __restrict__ w3)
{
    const int blk = blockIdx.x;
    if (blk < NX2_BLK) {
        const int i = blk * 256 + threadIdx.x;
        float2 v = x[i];
        *(uint32_t*)((__half2*)gx_h + i) = packh2(v.x, v.y);
    } else if (blk < NX2_BLK + 4 * NW2_BLK) {
        const int wsel = (blk - NX2_BLK) / NW2_BLK;
        const int i = ((blk - NX2_BLK) % NW2_BLK) * 256 + threadIdx.x;
        const float2* w = (wsel == 0) ? w0 : (wsel == 1) ? w1 : (wsel == 2) ? w2 : w3;
        float2 v = w[i];
        uint32_t h, l;
        splith2(v.x, v.y, h, l);
        const size_t off = (size_t)wsel << 19;
        *(uint32_t*)((__half2*)gw_h + off + i) = h;
        *(uint32_t*)((__half2*)gw_l + off + i) = l;
    } else {
        const int idx = (blk - NX2_BLK - 4 * NW2_BLK) * 256 + threadIdx.x;
        const int t = idx >> 5;
        const int i = idx & 31;
        double inv = pow(10000.0, -((double)(2 * i)) / 64.0);
        double ang = (double)t * inv;
        g_cos[idx] = (float)cos(ang);
        g_sin[idx] = (float)sin(ang);
    }
}

// ---------------- mma.sync fp16 2-pass GEMM: C = A * W^T -----------------------
// CTA tile 128x128, 8 warps (2x4), warp tile 64x32, K chunks of 64.
// Tiles per chunk: Ah, Wh, Wl. 2 stages, 2 CTAs/SM.
#define ROWB     144
#define TILE_B   (128 * ROWB)                // 18432
#define STAGE_B  (3 * TILE_B)                // 55296
#define GEMM_SMEM (2 * STAGE_B)              // 110592

template <int QKV>
__global__ void __launch_bounds__(256, 2)
mma_gemm(float* __restrict__ Cout)
{
    extern __shared__ char smem_raw[];
    const uint32_t sb = smem_u32(smem_raw);

    const int tid = threadIdx.x;
    const int wid = tid >> 5;
    const int lid = tid & 31;
    const int n0 = blockIdx.x * 128;
    const int m0 = blockIdx.y * 128;
    const int z  = QKV ? (int)blockIdx.z : 3;

    const __half* Ah = QKV ? gx_h : gctx_h;
    const __half* Wh = gw_h + ((size_t)z << 20);
    const __half* Wl = gw_l + ((size_t)z << 20);

    const __half* Ah_m = Ah + (size_t)m0 * DMD;
    const __half* Wh_n = Wh + (size_t)n0 * DMD;
    const __half* Wl_n = Wl + (size_t)n0 * DMD;

    const int llr = tid >> 3;            // 0..31
    const int llc = tid & 7;             // 0..7

    auto load_chunk = [&](int kc, int s) {
        const uint32_t stage = sb + (uint32_t)s * STAGE_B;
        const size_t koff = (size_t)kc * 64 + (size_t)llc * 8;
#pragma unroll
        for (int it = 0; it < 12; ++it) {
            const __half* base = (it < 4) ? Ah_m : (it < 8) ? Wh_n : Wl_n;
            const int r = (it & 3) * 32 + llr;
            const uint32_t dst = stage + (uint32_t)(it >> 2) * TILE_B
                               + (uint32_t)r * ROWB + (uint32_t)llc * 16;
            cp_async16(dst, base + (size_t)r * DMD + koff);
        }
        CP_COMMIT();
    };

    const int wm = wid >> 2;
    const int wn = wid & 3;
    const int lt  = lid >> 3;
    const int lrw = lid & 7;

    const uint32_t a_off = (uint32_t)(wm * 64 + (lt & 1) * 8 + lrw) * ROWB
                         + (uint32_t)(lt >> 1) * 16;
    const uint32_t b_off = (uint32_t)(wn * 32 + (lt & 1) * 8 + lrw) * ROWB
                         + (uint32_t)(lt >> 1) * 16;

    float acc[4][4][4];
#pragma unroll
    for (int i = 0; i < 4; i++)
#pragma unroll
        for (int j = 0; j < 4; j++)
#pragma unroll
            for (int r = 0; r < 4; r++) acc[i][j][r] = 0.0f;

    load_chunk(0, 0);

    for (int c = 0; c < 16; ++c) {
        const int s = c & 1;
        if (c < 15) {
            load_chunk(c + 1, s ^ 1);
            CP_WAIT(1);
        } else {
            CP_WAIT(0);
        }
        __syncthreads();

        const uint32_t stage = sb + (uint32_t)s * STAGE_B;
        const uint32_t ah_base = stage + a_off;
        const uint32_t bh_base = stage + TILE_B + b_off;
        const uint32_t bl_base = stage + 2 * TILE_B + b_off;

#pragma unroll
        for (int kk = 0; kk < 4; ++kk) {
            const uint32_t kb = (uint32_t)kk * 32;
            uint32_t ah[4][4], bh[2][4], bl[2][4];
#pragma unroll
            for (int mf = 0; mf < 4; ++mf) {
                LDMX4(ah[mf][0], ah[mf][1], ah[mf][2], ah[mf][3],
                      ah_base + (uint32_t)mf * (16 * ROWB) + kb);
            }
#pragma unroll
            for (int nn = 0; nn < 2; ++nn) {
                LDMX4(bh[nn][0], bh[nn][1], bh[nn][2], bh[nn][3],
                      bh_base + (uint32_t)nn * (16 * ROWB) + kb);
                LDMX4(bl[nn][0], bl[nn][1], bl[nn][2], bl[nn][3],
                      bl_base + (uint32_t)nn * (16 * ROWB) + kb);
            }
#pragma unroll
            for (int mf = 0; mf < 4; ++mf) {
#pragma unroll
                for (int nf = 0; nf < 4; ++nf) {
                    const int nn = nf >> 1;
                    const int sel = nf & 1;
                    MMA_F16(acc[mf][nf], ah[mf][0], ah[mf][1], ah[mf][2], ah[mf][3],
                            bh[nn][sel], bh[nn][2 + sel]);
                    MMA_F16(acc[mf][nf], ah[mf][0], ah[mf][1], ah[mf][2], ah[mf][3],
                            bl[nn][sel], bl[nn][2 + sel]);
                }
            }
        }
        __syncthreads();
    }

    // ---------------- epilogue ----------------
    const int rbase = m0 + wm * 64 + (lid >> 2);
    const int cbase = n0 + wn * 32 + (lid & 3) * 2;

#pragma unroll
    for (int mf = 0; mf < 4; ++mf) {
#pragma unroll
        for (int nf = 0; nf < 4; ++nf) {
#pragma unroll
            for (int half_ = 0; half_ < 2; ++half_) {
                const int m = rbase + mf * 16 + half_ * 8;
                const int n = cbase + nf * 8;
                const float x = acc[mf][nf][half_ * 2 + 0];
                const float y = acc[mf][nf][half_ * 2 + 1];
                if (QKV == 0) {
                    *(float2*)(Cout + (size_t)m * DMD + n) = make_float2(x, y);
                } else {
                    const int b = m >> 11;
                    const int t = m & (TT - 1);
                    const int h = n >> 6;
                    const int d = n & 63;
                    const size_t bh = (size_t)(b * HH + h);
                    if (z < 2) {
                        const float cs = g_cos[t * 32 + (d >> 1)];
                        const float sn = g_sin[t * 32 + (d >> 1)];
                        float rx = x * cs - y * sn;
                        float ry = x * sn + y * cs;
                        const size_t idx = (bh * TT + t) * DKD + d;
                        if (z == 0) {
                            // Q: A-side, hi only, scale folded
                            *(uint32_t*)(g_qh + idx) = packh2(rx * 0.125f, ry * 0.125f);
                        } else {
                            // K: B-side, hi + lo
                            uint32_t hv, lv;
                            splith2(rx, ry, hv, lv);
                            *(uint32_t*)(g_kh + idx) = hv;
                            *(uint32_t*)(g_kl + idx) = lv;
                        }
                    } else {
                        // V transposed [b,h,d,t]: B-side, hi + lo
                        __half hx = __float2half_rn(x);
                        __half hy = __float2half_rn(y);
                        const size_t ix = (bh * DKD + d) * TT + t;
                        g_vth[ix]      = hx;
                        g_vtl[ix]      = __float2half_rn(x - __half2float(hx));
                        g_vth[ix + TT] = hy;
                        g_vtl[ix + TT] = __float2half_rn(y - __half2float(hy));
                    }
                }
            }
        }
    }
}

// ---------------- tensor-core causal flash attention (fp16 2-pass) -------------
#define AROWB 144
#define ATILE (64 * AROWB)                 // 9216
#define ATT_SMEM (ATILE + 8 * ATILE)       // 82944: Qh + 2 stages * (Kh,Kl,Vh,Vl)

__global__ void __launch_bounds__(128, 2)
attn_kernel()
{
    extern __shared__ char smem_raw[];
    const uint32_t sb = smem_u32(smem_raw);
    const uint32_t stages = sb + ATILE;

    const int h   = blockIdx.x;
    const int b   = blockIdx.y;
    const int qt  = (int)(gridDim.z - 1 - blockIdx.z);   // heavy tiles first
    const int tid = threadIdx.x;
    const int wq  = tid >> 5;
    const int lid = tid & 31;

    const size_t bh = (size_t)(b * HH + h);
    const __half* qh_g = g_qh + (bh * TT + (size_t)qt * 64) * DKD;
    const __half* kh_g = g_kh + bh * TT * DKD;
    const __half* kl_g = g_kl + bh * TT * DKD;
    const __half* vh_g = g_vth + bh * DKD * TT;
    const __half* vl_g = g_vtl + bh * DKD * TT;

    // ---- load Q tile (hi only) ----
#pragma unroll
    for (int i = 0; i < 4; ++i) {
        int cid = i * 128 + tid;
        int r = cid >> 3, c = cid & 7;
        cp_async16(sb + (uint32_t)r * AROWB + (uint32_t)c * 16,
                   qh_g + (size_t)r * DKD + c * 8);
    }
    CP_COMMIT();

    auto load_kv = [&](int kt, int s) {
        const uint32_t stage = stages + (uint32_t)s * (4 * ATILE);
#pragma unroll
        for (int i = 0; i < 4; ++i) {
            int cid = i * 128 + tid;
            int r = cid >> 3, c = cid & 7;
            const uint32_t so = (uint32_t)r * AROWB + (uint32_t)c * 16;
            const size_t kk = (size_t)(kt * 64 + r) * DKD + c * 8;
            const size_t vv = (size_t)r * TT + kt * 64 + c * 8;
            cp_async16(stage + so,             kh_g + kk);
            cp_async16(stage + ATILE + so,     kl_g + kk);
            cp_async16(stage + 2 * ATILE + so, vh_g + vv);
            cp_async16(stage + 3 * ATILE + so, vl_g + vv);
        }
        CP_COMMIT();
    };

    const int lt  = lid >> 3;
    const int lrw = lid & 7;
    const uint32_t a_off = (uint32_t)(wq * 16 + (lt & 1) * 8 + lrw) * AROWB
                         + (uint32_t)(lt >> 1) * 16;
    uint32_t bn_off[4];
#pragma unroll
    for (int nn = 0; nn < 4; ++nn)
        bn_off[nn] = (uint32_t)(nn * 16 + (lt & 1) * 8 + lrw) * AROWB
                   + (uint32_t)(lt >> 1) * 16;

    load_kv(0, 0);

    CP_WAIT(1);
    __syncthreads();
    uint32_t qf[4][4];
#pragma unroll
    for (int ks = 0; ks < 4; ++ks) {
        LDMX4(qf[ks][0], qf[ks][1], qf[ks][2], qf[ks][3], sb + a_off + ks * 32);
    }

    float O[8][4];
#pragma unroll
    for (int i = 0; i < 8; ++i)
#pragma unroll
        for (int j = 0; j < 4; ++j) O[i][j] = 0.0f;
    float m0v = -1e30f, m1v = -1e30f, l0 = 0.0f, l1 = 0.0f;

    for (int kt = 0; kt <= qt; ++kt) {
        const int s = kt & 1;
        if (kt < qt) {
            load_kv(kt + 1, s ^ 1);
            CP_WAIT(1);
        } else {
            CP_WAIT(0);
        }
        __syncthreads();

        const uint32_t stage = stages + (uint32_t)s * (4 * ATILE);

        // ---- S = Q K^T (2-pass: Qh·Kh + Qh·Kl) ----
        float S[8][4];
#pragma unroll
        for (int i = 0; i < 8; ++i)
#pragma unroll
            for (int j = 0; j < 4; ++j) S[i][j] = 0.0f;

#pragma unroll
        for (int ks = 0; ks < 4; ++ks) {
            uint32_t kh[4][4], kl[4][4];
#pragma unroll
            for (int nn = 0; nn < 4; ++nn) {
                LDMX4(kh[nn][0], kh[nn][1], kh[nn][2], kh[nn][3],
                      stage + bn_off[nn] + ks * 32);
                LDMX4(kl[nn][0], kl[nn][1], kl[nn][2], kl[nn][3],
                      stage + ATILE + bn_off[nn] + ks * 32);
            }
#pragma unroll
            for (int nf = 0; nf < 8; ++nf) {
                const int nn = nf >> 1;
                const int sel = nf & 1;
                MMA_F16(S[nf], qf[ks][0], qf[ks][1], qf[ks][2], qf[ks][3],
                        kh[nn][sel], kh[nn][2 + sel]);
                MMA_F16(S[nf], qf[ks][0], qf[ks][1], qf[ks][2], qf[ks][3],
                        kl[nn][sel], kl[nn][2 + sel]);
            }
        }

        // ---- causal mask on diagonal tile ----
        if (kt == qt) {
            const int row0 = wq * 16 + (lid >> 2);
            const int colb = (lid & 3) * 2;
#pragma unroll
            for (int nf = 0; nf < 8; ++nf) {
                const int c0 = nf * 8 + colb;
                if (c0     > row0)     S[nf][0] = -1e30f;
                if (c0 + 1 > row0)     S[nf][1] = -1e30f;
                if (c0     > row0 + 8) S[nf][2] = -1e30f;
                if (c0 + 1 > row0 + 8) S[nf][3] = -1e30f;
            }
        }

        // ---- online softmax ----
        float r0 = -1e30f, r1 = -1e30f;
#pragma unroll
        for (int nf = 0; nf < 8; ++nf) {
            r0 = fmaxf(r0, fmaxf(S[nf][0], S[nf][1]));
            r1 = fmaxf(r1, fmaxf(S[nf][2], S[nf][3]));
        }
        r0 = fmaxf(r0, __shfl_xor_sync(0xffffffffu, r0, 1));
        r0 = fmaxf(r0, __shfl_xor_sync(0xffffffffu, r0, 2));
        r1 = fmaxf(r1, __shfl_xor_sync(0xffffffffu, r1, 1));
        r1 = fmaxf(r1, __shfl_xor_sync(0xffffffffu, r1, 2));

        const float nm0 = fmaxf(m0v, r0);
        const float nm1 = fmaxf(m1v, r1);
        const float a0 = __expf(m0v - nm0);
        const float a1 = __expf(m1v - nm1);
        m0v = nm0; m1v = nm1;

        float rs0 = 0.0f, rs1 = 0.0f;
#pragma unroll
        for (int nf = 0; nf < 8; ++nf) {
            S[nf][0] = __expf(S[nf][0] - m0v);
            S[nf][1] = __expf(S[nf][1] - m0v);
            S[nf][2] = __expf(S[nf][2] - m1v);
            S[nf][3] = __expf(S[nf][3] - m1v);
            rs0 += S[nf][0] + S[nf][1];
            rs1 += S[nf][2] + S[nf][3];
        }
        rs0 += __shfl_xor_sync(0xffffffffu, rs0, 1);
        rs0 += __shfl_xor_sync(0xffffffffu, rs0, 2);
        rs1 += __shfl_xor_sync(0xffffffffu, rs1, 1);
        rs1 += __shfl_xor_sync(0xffffffffu, rs1, 2);
        l0 = l0 * a0 + rs0;
        l1 = l1 * a1 + rs1;

#pragma unroll
        for (int nf = 0; nf < 8; ++nf) {
            O[nf][0] *= a0; O[nf][1] *= a0;
            O[nf][2] *= a1; O[nf][3] *= a1;
        }

        // ---- PV (2-pass: Ph·Vh + Ph·Vl) ----
#pragma unroll
        for (int kb2 = 0; kb2 < 4; ++kb2) {
            uint32_t ph[4];
            ph[0] = packh2(S[2 * kb2][0],     S[2 * kb2][1]);
            ph[1] = packh2(S[2 * kb2][2],     S[2 * kb2][3]);
            ph[2] = packh2(S[2 * kb2 + 1][0], S[2 * kb2 + 1][1]);
            ph[3] = packh2(S[2 * kb2 + 1][2], S[2 * kb2 + 1][3]);

            uint32_t vh[4][4], vl[4][4];
#pragma unroll
            for (int nn = 0; nn < 4; ++nn) {
                LDMX4(vh[nn][0], vh[nn][1], vh[nn][2], vh[nn][3],
                      stage + 2 * ATILE + bn_off[nn] + kb2 * 32);
                LDMX4(vl[nn][0], vl[nn][1], vl[nn][2], vl[nn][3],
                      stage + 3 * ATILE + bn_off[nn] + kb2 * 32);
            }
#pragma unroll
            for (int nf = 0; nf < 8; ++nf) {
                const int nn = nf >> 1;
                const int sel = nf & 1;
                MMA_F16(O[nf], ph[0], ph[1], ph[2], ph[3],
                        vh[nn][sel], vh[nn][2 + sel]);
                MMA_F16(O[nf], ph[0], ph[1], ph[2], ph[3],
                        vl[nn][sel], vl[nn][2 + sel]);
            }
        }
        __syncthreads();
    }

    // ---- epilogue: ctx fp16 hi (A-side of O-projection) ----
    const float i0 = 1.0f / l0;
    const float i1 = 1.0f / l1;
    const int q0 = qt * 64 + wq * 16 + (lid >> 2);
    const int colb = (lid & 3) * 2;
#pragma unroll
    for (int nf = 0; nf < 8; ++nf) {
        const int d = nf * 8 + colb;
        size_t idx = ((size_t)b * TT + q0) * DMD + h * DKD + d;
        *(uint32_t*)(gctx_h + idx) = packh2(O[nf][0] * i0, O[nf][1] * i0);
        idx += (size_t)8 * DMD;
        *(uint32_t*)(gctx_h + idx) = packh2(O[nf][2] * i1, O[nf][3] * i1);
    }
}

// ---------------- launch ---------------------------------------------------------
extern "C" void kernel_launch(void* const* d_in, const int* in_sizes, int n_in,
                              void* d_out, int out_size)
{
    const float* x   = (const float*)d_in[0];
    const float* w_q = (const float*)d_in[1];
    const float* w_k = (const float*)d_in[2];
    const float* w_v = (const float*)d_in[3];
    const float* w_o = (const float*)d_in[4];
    float* out = (float*)d_out;

    static int configured = 0;
    if (!configured) {
        cudaFuncSetAttribute(mma_gemm<1>, cudaFuncAttributeMaxDynamicSharedMemorySize, GEMM_SMEM);
        cudaFuncSetAttribute(mma_gemm<0>, cudaFuncAttributeMaxDynamicSharedMemorySize, GEMM_SMEM);
        cudaFuncSetAttribute(attn_kernel, cudaFuncAttributeMaxDynamicSharedMemorySize, ATT_SMEM);
        configured = 1;
    }

    prep_kernel<<<PREP_BLOCKS, 256>>>((const float2*)x, (const float2*)w_q,
                                      (const float2*)w_k, (const float2*)w_v,
                                      (const float2*)w_o);

    mma_gemm<1><<<dim3(DMD / 128, MTOT / 128, 3), 256, GEMM_SMEM>>>(nullptr);

    attn_kernel<<<dim3(HH, BB, TT / 64), 128, ATT_SMEM>>>();

    mma_gemm<0><<<dim3(DMD / 128, MTOT / 128, 1), 256, GEMM_SMEM>>>(out);
}